// round 16
// baseline (speedup 1.0000x reference)
#include <cuda_runtime.h>
#include <cstdint>

// ---------------------------------------------------------------------------
// RipsECC. B=4096 points in [0,1]^3, 64 bins, bin(d) = ceil(31.5*d) in [0,55].
// All C(4096,2)=8,386,560 pairs are edges. out = cumsum(+4096 at bin0 - hist).
//
// R15 chassis (148 x 1024, 1 CTA/SM, pts float4 prescaled x31.5 + norm,
// 4-i register blocking, MUFU.SQRT + F2I.RU binning, u8 hist 64KB with
// dp4a reduce, g_part+ticket tail) with a BALANCED unit grid:
//  * 256 diagonal units: u<256 -> s=u>>3, chunk c=u&7 (16 predicated j).
//  * 4247 off-diagonal 15-step units: per sb s, ceil((3968-128s)/15) chunks;
//    prefix table in __constant__ (hand-verified); decode = float guess +
//    table fixup. Tail padding: per-step j<4096 predicate; OOB pts reads
//    (<= pts[4110]) land in the hist region (garbage floats) and their
//    increments are predicated off -> safe + deterministic.
//  * NUNITS = 4503 over 4736 warp slots (95% busy; crit path 16 -> 15 steps
//    for 94% of units).
// ---------------------------------------------------------------------------

#define NPTS      4096
#define NSTEPS    64
#define NTHREADS  1024
#define NBLOCKS   148
#define NDIAG     256
#define NUNITS    4503
#define NREGIONS  8
#define HIST_WORDS (NREGIONS * NSTEPS * 32)        // 16384 words = 64 KB
#define SMEM_BYTES (NPTS * 16 + HIST_WORDS * 4)    // 64KB + 64KB = 131072

__device__ int      g_part[NBLOCKS][NSTEPS];
__device__ unsigned g_ticket = 0;

// Prefix of off-diagonal unit counts: P(s) = sum_{k<s} ceil((3968-128k)/15).
__constant__ int c_poff[33] = {
       0,  265,  521,  769, 1008, 1239, 1461, 1675, 1880, 2077, 2265,
    2445, 2616, 2779, 2933, 3079, 3216, 3344, 3464, 3575, 3678, 3772,
    3858, 3935, 4004, 4064, 4116, 4159, 4194, 4220, 4238, 4247, 4247};

extern __shared__ float4 smem4[];

// t = ceil(sqrt(m)); F2I.RU(NaN) = 0 keeps the index bounded.
__device__ __forceinline__ int bin_t(float A, float B, float C, float Kw,
                                     float4 p) {
    float m = fmaf(A, p.x, fmaf(B, p.y, fmaf(C, p.z, Kw)));
    float d;
    asm("sqrt.approx.f32 %0, %1;" : "=f"(d) : "f"(m));   // MUFU.SQRT
    return __float2int_ru(d);
}

__global__ void __launch_bounds__(NTHREADS, 1)
rips_ecc_kernel(const float* __restrict__ x, float* __restrict__ out) {
    float4*        pts  = smem4;                       // [4096] x31.5 + norm
    unsigned*      hist = (unsigned*)(smem4 + NPTS);   // [8][64][32] words
    unsigned char* h8   = (unsigned char*)hist;

    const int tid = threadIdx.x;

    // Stage points: thread t computes points 4t..4t+3 from 3 LDG.128.
    {
        const float4* xv = (const float4*)x;           // 3072 float4
        float4 v0 = xv[3 * tid + 0];
        float4 v1 = xv[3 * tid + 1];
        float4 v2 = xv[3 * tid + 2];
        float px, py, pz;
        px = 31.5f * v0.x; py = 31.5f * v0.y; pz = 31.5f * v0.z;
        pts[4 * tid + 0] = make_float4(px, py, pz,
                                       fmaf(px, px, fmaf(py, py, pz * pz)));
        px = 31.5f * v0.w; py = 31.5f * v1.x; pz = 31.5f * v1.y;
        pts[4 * tid + 1] = make_float4(px, py, pz,
                                       fmaf(px, px, fmaf(py, py, pz * pz)));
        px = 31.5f * v1.z; py = 31.5f * v1.w; pz = 31.5f * v2.x;
        pts[4 * tid + 2] = make_float4(px, py, pz,
                                       fmaf(px, px, fmaf(py, py, pz * pz)));
        px = 31.5f * v2.y; py = 31.5f * v2.z; pz = 31.5f * v2.w;
        pts[4 * tid + 3] = make_float4(px, py, pz,
                                       fmaf(px, px, fmaf(py, py, pz * pz)));
    }
    // Zero the FULL 64KB histogram: 4096 uint4 = 4 x STS.128 per thread.
    {
        uint4* h4 = (uint4*)hist;
        #pragma unroll
        for (int i = 0; i < HIST_WORDS / 4 / NTHREADS; i++)   // 4 iterations
            h4[i * NTHREADS + tid] = make_uint4(0u, 0u, 0u, 0u);
    }
    __syncthreads();

    const int warp = tid >> 5;   // 0..31
    const int lane = tid & 31;
    // u8 slot: region = warp>>2 (8192 B each), byte = lane*4 + (warp&3).
    unsigned char* myh = h8 + (warp >> 2) * 8192 + lane * 4 + (warp & 3);

    const int u = warp * NBLOCKS + blockIdx.x;         // [0, 4736)
    if (u < NUNITS) {
        int sbase, rem_is_diag_chunk = -1, j0 = 0;
        if (u < NDIAG) {
            sbase = (u >> 3) << 7;
            rem_is_diag_chunk = u & 7;                 // diagonal chunk 0..7
        } else {
            int v = u - NDIAG;                         // 0..4246
            // Smooth inverse of P(s) ~ (4032s - 64s^2)/15, then table fixup.
            float arg = (float)(16257024 - 3840 * v);
            int s = (int)((4032.0f - sqrtf(fmaxf(arg, 0.0f))) * (1.0f/128.0f));
            s = max(0, min(31, s));
            while (s > 0 && c_poff[s] > v) --s;
            while (c_poff[s + 1] <= v) ++s;            // c_poff[32]=4247 > v
            sbase = s << 7;
            j0 = sbase + 128 + 15 * (v - c_poff[s]);
        }

        float4 q0 = pts[sbase + lane];
        float4 q1 = pts[sbase + 32 + lane];
        float4 q2 = pts[sbase + 64 + lane];
        float4 q3 = pts[sbase + 96 + lane];
        const float A0 = -2.0f*q0.x, B0 = -2.0f*q0.y, C0 = -2.0f*q0.z, K0 = q0.w;
        const float A1 = -2.0f*q1.x, B1 = -2.0f*q1.y, C1 = -2.0f*q1.z, K1 = q1.w;
        const float A2 = -2.0f*q2.x, B2 = -2.0f*q2.y, C2 = -2.0f*q2.z, K2 = q2.w;
        const float A3 = -2.0f*q3.x, B3 = -2.0f*q3.y, C3 = -2.0f*q3.z, K3 = q3.w;

        if (rem_is_diag_chunk >= 0) {
            // Diagonal chunk: jrel = 16*c + jj; count (i_q, j) iff
            // jrel > 32q + lane.
            const int jr0 = rem_is_diag_chunk << 4;
            #pragma unroll
            for (int jj = 0; jj < 16; jj++) {
                int jrel = jr0 + jj;
                float4 p = pts[sbase + jrel];
                int t0 = bin_t(A0, B0, C0, K0 + p.w, p);
                int t1 = bin_t(A1, B1, C1, K1 + p.w, p);
                int t2 = bin_t(A2, B2, C2, K2 + p.w, p);
                int t3 = bin_t(A3, B3, C3, K3 + p.w, p);
                if (jrel > lane)      myh[t0 << 7] += (unsigned char)1;
                if (jrel > lane + 32) myh[t1 << 7] += (unsigned char)1;
                if (jrel > lane + 64) myh[t2 << 7] += (unsigned char)1;
                if (jrel > lane + 96) myh[t3 << 7] += (unsigned char)1;
            }
        } else {
            // Off-diagonal 15-step unit; tail steps (j >= 4096) predicated.
            #pragma unroll
            for (int jj = 0; jj < 15; jj++) {
                int j = j0 + jj;                       // may reach 4110: the
                float4 p = pts[j];                     // read lands in hist
                int t0 = bin_t(A0, B0, C0, K0 + p.w, p);   // region; harmless,
                int t1 = bin_t(A1, B1, C1, K1 + p.w, p);   // increments are
                int t2 = bin_t(A2, B2, C2, K2 + p.w, p);   // predicated off.
                int t3 = bin_t(A3, B3, C3, K3 + p.w, p);
                if (j < NPTS) {
                    myh[t0 << 7] += (unsigned char)1;
                    myh[t1 << 7] += (unsigned char)1;
                    myh[t2 << 7] += (unsigned char)1;
                    myh[t3 << 7] += (unsigned char)1;
                }
            }
        }
    }
    __syncthreads();

    // Block reduction: warp w reduces bins {2w, 2w+1}; dp4a sums the 4
    // byte-banks per word across 8 regions; write per-block partials.
    #pragma unroll
    for (int bb = 0; bb < 2; bb++) {
        int bin = warp * 2 + bb;
        int sa = 0;
        #pragma unroll
        for (int r = 0; r < NREGIONS; r++)
            sa = __dp4a((int)hist[r * 2048 + (bin << 5) + lane], 0x01010101, sa);
        #pragma unroll
        for (int o = 16; o > 0; o >>= 1)
            sa += __shfl_down_sync(0xffffffffu, sa, o);
        if (lane == 0)
            g_part[blockIdx.x][bin] = sa;
    }
    __threadfence();
    __syncthreads();

    __shared__ int s_last;
    if (tid == 0)
        s_last = (atomicAdd(&g_ticket, 1u) == NBLOCKS - 1);
    __syncthreads();
    if (!s_last) return;
    __threadfence();

    // --- last block: reduce 148x64 partials, cumsum, write, reset ticket ---
    __shared__ int red[NSTEPS * 16];
    {
        int bin = tid & 63;
        int grp = tid >> 6;               // 0..15
        int sa = 0;
        for (int b2 = grp; b2 < NBLOCKS; b2 += 16)
            sa += g_part[b2][bin];
        red[bin * 16 + grp] = sa;
    }
    __syncthreads();
    __shared__ int ecc[NSTEPS];
    if (tid < NSTEPS) {
        int tot = 0;
        #pragma unroll
        for (int g = 0; g < 16; g++) tot += red[tid * 16 + g];
        ecc[tid] = (tid == 0 ? NPTS : 0) - tot;
    }
    __syncthreads();
    if (tid < 32) {
        int e0 = ecc[tid];
        int e1 = ecc[tid + 32];
        #pragma unroll
        for (int d = 1; d < 32; d <<= 1) {
            int t = __shfl_up_sync(0xffffffffu, e0, d);
            if (tid >= d) e0 += t;
        }
        int tot = __shfl_sync(0xffffffffu, e0, 31);
        #pragma unroll
        for (int d = 1; d < 32; d <<= 1) {
            int t = __shfl_up_sync(0xffffffffu, e1, d);
            if (tid >= d) e1 += t;
        }
        e1 += tot;
        out[tid]      = (float)e0;
        out[tid + 32] = (float)e1;
    }
    if (tid == 0) g_ticket = 0;   // self-reset for graph replay
}

extern "C" void kernel_launch(void* const* d_in, const int* in_sizes, int n_in,
                              void* d_out, int out_size) {
    (void)in_sizes; (void)n_in; (void)out_size;
    const float* x = (const float*)d_in[0];
    float* out = (float*)d_out;

    cudaFuncSetAttribute(rips_ecc_kernel,
                         cudaFuncAttributeMaxDynamicSharedMemorySize, SMEM_BYTES);

    rips_ecc_kernel<<<NBLOCKS, NTHREADS, SMEM_BYTES>>>(x, out);
}